// round 1
// baseline (speedup 1.0000x reference)
#include <cuda_runtime.h>
#include <math.h>
#include <stdint.h>

#define IMGSZ 512
#define TOPN 1000
#define BBOX_CLAMP 4.135166556742356f

// ---------------- scratch (device globals; no allocation allowed) ----------------
__device__ float g_c0[64*256*256];     // after conv0+relu
__device__ float g_pool[64*128*128];   // after maxpool
__device__ float g_c1[128*64*64];
__device__ float g_c2[256*32*32];
__device__ float g_feat[512*16*16];
__device__ float g_rpn[512*16*16];
__device__ float g_obj[9*16*16];
__device__ float g_bd[36*16*16];
__device__ float g_props[2304*4];
__device__ float g_scores[2304];
__device__ int   g_topidx[TOPN];
__device__ float g_rois[TOPN*4];
__device__ float g_bf[TOPN*25088];     // roi-aligned features (1000 x 25088)
__device__ float g_h1[TOPN*1024];
__device__ float g_h2[TOPN*1024];
__device__ float g_logits[TOPN*6];
__device__ float g_breg[TOPN*24];

// ---------------- conv0: 7x7 s2 p3, 3->64, 512^2 -> 256^2, fused normalize+relu ----------------
__global__ void conv0_kernel(const float* __restrict__ img,
                             const float* __restrict__ w,
                             const float* __restrict__ b,
                             float* __restrict__ out) {
    __shared__ float ws[3*49];
    int o = blockIdx.z;
    int tid = threadIdx.y * 16 + threadIdx.x;
    if (tid < 147) ws[tid] = w[o*147 + tid];
    __syncthreads();
    int x = blockIdx.x * 16 + threadIdx.x;
    int y = blockIdx.y * 16 + threadIdx.y;
    const float mean[3] = {0.485f, 0.456f, 0.406f};
    const float stdv[3] = {0.229f, 0.224f, 0.225f};
    float acc = b[o];
    #pragma unroll
    for (int c = 0; c < 3; c++) {
        float istd = 1.0f / stdv[c];
        #pragma unroll
        for (int ky = 0; ky < 7; ky++) {
            int iy = 2*y - 3 + ky;
            if (iy < 0 || iy >= 512) continue;
            #pragma unroll
            for (int kx = 0; kx < 7; kx++) {
                int ix = 2*x - 3 + kx;
                if (ix < 0 || ix >= 512) continue;
                float v = (img[(c*512 + iy)*512 + ix] - mean[c]) * istd;
                acc = fmaf(v, ws[c*49 + ky*7 + kx], acc);
            }
        }
    }
    out[(o*256 + y)*256 + x] = fmaxf(acc, 0.0f);
}

// ---------------- maxpool 3x3 s2 p1: 64x256^2 -> 64x128^2 ----------------
__global__ void maxpool_kernel(const float* __restrict__ in, float* __restrict__ out) {
    int idx = blockIdx.x * 256 + threadIdx.x;
    if (idx >= 64*128*128) return;
    int x = idx & 127;
    int y = (idx >> 7) & 127;
    int c = idx >> 14;
    float m = -INFINITY;
    #pragma unroll
    for (int dy = 0; dy < 3; dy++) {
        int iy = 2*y - 1 + dy;
        if (iy < 0 || iy >= 256) continue;
        #pragma unroll
        for (int dx = 0; dx < 3; dx++) {
            int ix = 2*x - 1 + dx;
            if (ix < 0 || ix >= 256) continue;
            m = fmaxf(m, in[(c*256 + iy)*256 + ix]);
        }
    }
    out[idx] = m;
}

// ---------------- generic 3x3 conv (pad 1), weights in smem, relu ----------------
__global__ void conv3x3_kernel(const float* __restrict__ in,
                               const float* __restrict__ w,
                               const float* __restrict__ b,
                               float* __restrict__ out,
                               int Cin, int Hin, int Hout, int stride) {
    extern __shared__ float ws[];
    int o = blockIdx.z;
    int nth = blockDim.x * blockDim.y;
    int tid = threadIdx.y * blockDim.x + threadIdx.x;
    for (int i = tid; i < Cin*9; i += nth) ws[i] = w[o*Cin*9 + i];
    __syncthreads();
    int x = blockIdx.x * blockDim.x + threadIdx.x;
    int y = blockIdx.y * blockDim.y + threadIdx.y;
    if (x >= Hout || y >= Hout) return;
    float acc = b[o];
    int iy0 = y*stride - 1, ix0 = x*stride - 1;
    for (int c = 0; c < Cin; c++) {
        const float* ip = in + c*Hin*Hin;
        const float* wp = ws + c*9;
        #pragma unroll
        for (int ky = 0; ky < 3; ky++) {
            int iy = iy0 + ky;
            if (iy < 0 || iy >= Hin) continue;
            #pragma unroll
            for (int kx = 0; kx < 3; kx++) {
                int ix = ix0 + kx;
                if (ix < 0 || ix >= Hin) continue;
                acc = fmaf(ip[iy*Hin + ix], wp[ky*3 + kx], acc);
            }
        }
    }
    out[(o*Hout + y)*Hout + x] = fmaxf(acc, 0.0f);
}

// ---------------- 1x1 conv over 16x16 plane (no relu) ----------------
__global__ void conv1x1_kernel(const float* __restrict__ in,
                               const float* __restrict__ w,
                               const float* __restrict__ b,
                               float* __restrict__ out, int Cin) {
    int p = threadIdx.x;  // 256 spatial positions
    int o = blockIdx.x;
    float acc = b[o];
    for (int c = 0; c < Cin; c++)
        acc = fmaf(in[c*256 + p], w[o*Cin + c], acc);
    out[o*256 + p] = acc;
}

// ---------------- RPN anchor decode: props + scores ----------------
__global__ void rpn_decode_kernel(const float* __restrict__ obj,
                                  const float* __restrict__ bd,
                                  float* __restrict__ props,
                                  float* __restrict__ scores) {
    int i = blockIdx.x * 256 + threadIdx.x;
    if (i >= 2304) return;
    int a = i % 9;
    int cell = i / 9;
    int wq = cell % 16;
    int hq = cell / 16;
    int pix = hq*16 + wq;
    scores[i] = obj[a*256 + pix];

    const float ratios[3] = {0.5f, 1.0f, 2.0f};
    int r = a / 3, s = a % 3;
    float scale = 128.0f * (float)(1 << s);
    float hr = sqrtf(ratios[r]);
    float wr = 1.0f / hr;
    float hw = rintf(wr * scale * 0.5f);   // np.round (half-even) of ws/2
    float hh = rintf(hr * scale * 0.5f);
    float sx = (float)(wq * 32), sy = (float)(hq * 32);
    float ax1 = sx - hw, ay1 = sy - hh, ax2 = sx + hw, ay2 = sy + hh;
    float W = ax2 - ax1, H = ay2 - ay1;
    float cx = ax1 + 0.5f*W, cy = ay1 + 0.5f*H;

    float dx = bd[(a*4+0)*256 + pix];
    float dy = bd[(a*4+1)*256 + pix];
    float dw = fminf(bd[(a*4+2)*256 + pix], BBOX_CLAMP);
    float dh = fminf(bd[(a*4+3)*256 + pix], BBOX_CLAMP);
    float pcx = dx*W + cx, pcy = dy*H + cy;
    float pw = expf(dw)*W, ph = expf(dh)*H;
    props[i*4+0] = pcx - 0.5f*pw;
    props[i*4+1] = pcy - 0.5f*ph;
    props[i*4+2] = pcx + 0.5f*pw;
    props[i*4+3] = pcy + 0.5f*ph;
}

// ---------------- top-k (1000 of 2304): single-block bitonic sort over 4096 ----------------
// Order: descending score, ties -> ascending index (matches lax.top_k).
__device__ __forceinline__ bool tk_lt(float sa, int ia, float sb, int ib) {
    return (sa > sb) || (sa == sb && ia < ib);
}
__global__ void topk_kernel(const float* __restrict__ scores, int* __restrict__ topidx) {
    __shared__ float s[4096];
    __shared__ int   ind[4096];
    int tid = threadIdx.x;
    for (int i = tid; i < 4096; i += 1024) {
        s[i] = (i < 2304) ? scores[i] : -INFINITY;
        ind[i] = i;
    }
    __syncthreads();
    for (int k = 2; k <= 4096; k <<= 1) {
        for (int j = k >> 1; j > 0; j >>= 1) {
            for (int base = 0; base < 4096; base += 1024) {
                int i = base + tid;
                int ixj = i ^ j;
                if (ixj > i) {
                    bool up = ((i & k) == 0);
                    float si = s[i], sj = s[ixj];
                    int ii = ind[i], ij = ind[ixj];
                    bool swp = up ? tk_lt(sj, ij, si, ii) : tk_lt(si, ii, sj, ij);
                    if (swp) { s[i] = sj; s[ixj] = si; ind[i] = ij; ind[ixj] = ii; }
                }
            }
            __syncthreads();
        }
    }
    for (int i = tid; i < TOPN; i += 1024) topidx[i] = ind[i];
}

// ---------------- gather + clip rois ----------------
__global__ void gather_rois_kernel(const float* __restrict__ props,
                                   const int* __restrict__ topidx,
                                   float* __restrict__ rois) {
    int i = blockIdx.x * 256 + threadIdx.x;
    if (i >= TOPN) return;
    int idx = topidx[i];
    #pragma unroll
    for (int k = 0; k < 4; k++)
        rois[i*4+k] = fminf(fmaxf(props[idx*4+k], 0.0f), 512.0f);
}

// ---------------- ROI align: feat (512,16,16) CHW, 14x14 samples -> 2x2 mean -> 7x7 ----------------
__global__ void roi_align_kernel(const float* __restrict__ feat,
                                 const float* __restrict__ rois,
                                 float* __restrict__ bf) {
    __shared__ int   sx0[14], sx1[14], sy0[14], sy1[14];
    __shared__ float slx[14], sly[14];
    int r = blockIdx.x;
    int tid = threadIdx.x;
    if (tid < 28) {
        int i = tid % 14;
        bool isY = tid >= 14;
        float c1 = rois[r*4 + (isY ? 1 : 0)];
        float c2 = rois[r*4 + (isY ? 3 : 2)];
        float lo = c1 * (1.0f/32.0f);
        float hi = c2 * (1.0f/32.0f);
        float sz = fmaxf(hi - lo, 1.0f);
        float g = ((float)i + 0.5f) / 14.0f;
        float p = fminf(fmaxf(lo + g*sz, 0.0f), 15.0f);
        int p0 = (int)floorf(p);
        int p1 = min(p0 + 1, 15);
        float l = p - (float)p0;
        if (isY) { sy0[i] = p0; sy1[i] = p1; sly[i] = l; }
        else     { sx0[i] = p0; sx1[i] = p1; slx[i] = l; }
    }
    __syncthreads();
    for (int j = tid; j < 25088; j += 256) {
        int c = j / 49;
        int p = j % 49;
        int py = p / 7, px = p % 7;
        const float* fp = feat + c*256;
        float acc = 0.0f;
        #pragma unroll
        for (int dy = 0; dy < 2; dy++) {
            int iy = py*2 + dy;
            float ly = sly[iy], hy = 1.0f - ly;
            int y0 = sy0[iy], y1 = sy1[iy];
            #pragma unroll
            for (int dx = 0; dx < 2; dx++) {
                int ix = px*2 + dx;
                float lx = slx[ix], hx = 1.0f - lx;
                int x0 = sx0[ix], x1 = sx1[ix];
                acc += hy*hx*fp[y0*16+x0] + hy*lx*fp[y0*16+x1]
                     + ly*hx*fp[y1*16+x0] + ly*lx*fp[y1*16+x1];
            }
        }
        bf[(size_t)r*25088 + j] = acc * 0.25f;
    }
}

// ---------------- tiled SIMT GEMM: C[M,N] = A[M,K] @ B[K,N] + bias, optional relu ----------------
// BM=BN=64, BK=16, 256 threads, 4x4 per-thread tile. K % 16 == 0, N % 64 == 0.
__global__ void gemm_bias_kernel(const float* __restrict__ A,
                                 const float* __restrict__ B,
                                 const float* __restrict__ bias,
                                 float* __restrict__ C,
                                 int M, int N, int K, int relu) {
    __shared__ float As[16][65];
    __shared__ float Bs[16][65];
    int tid = threadIdx.x;
    int tx = tid & 15, ty = tid >> 4;
    int bm = blockIdx.y * 64, bn = blockIdx.x * 64;
    float acc[4][4] = {};
    for (int k0 = 0; k0 < K; k0 += 16) {
        #pragma unroll
        for (int l = 0; l < 4; l++) {
            int i = tid + l*256;
            int row = i >> 4, kk = i & 15;
            int gr = bm + row;
            As[kk][row] = (gr < M) ? A[(size_t)gr*K + k0 + kk] : 0.0f;
        }
        #pragma unroll
        for (int l = 0; l < 4; l++) {
            int i = tid + l*256;
            int kk = i >> 6, col = i & 63;
            Bs[kk][col] = B[(size_t)(k0 + kk)*N + bn + col];
        }
        __syncthreads();
        #pragma unroll
        for (int kk = 0; kk < 16; kk++) {
            float a[4], b[4];
            #pragma unroll
            for (int i = 0; i < 4; i++) a[i] = As[kk][ty + 16*i];
            #pragma unroll
            for (int j = 0; j < 4; j++) b[j] = Bs[kk][tx + 16*j];
            #pragma unroll
            for (int i = 0; i < 4; i++)
                #pragma unroll
                for (int j = 0; j < 4; j++)
                    acc[i][j] = fmaf(a[i], b[j], acc[i][j]);
        }
        __syncthreads();
    }
    #pragma unroll
    for (int i = 0; i < 4; i++) {
        int row = bm + ty + 16*i;
        if (row >= M) continue;
        #pragma unroll
        for (int j = 0; j < 4; j++) {
            int col = bn + tx + 16*j;
            float v = acc[i][j] + bias[col];
            if (relu) v = fmaxf(v, 0.0f);
            C[(size_t)row*N + col] = v;
        }
    }
}

// ---------------- cls + bbox heads (K=1024, N=6 and N=24) ----------------
__global__ void fc_small_kernel(const float* __restrict__ h,
                                const float* __restrict__ clsw, const float* __restrict__ clsb,
                                const float* __restrict__ bbw, const float* __restrict__ bbb,
                                float* __restrict__ logits, float* __restrict__ breg) {
    int t = blockIdx.x * 128 + threadIdx.x;
    if (t >= TOPN * 30) return;
    int r = t / 30, j = t % 30;
    const float* hp = h + r*1024;
    if (j < 6) {
        float acc = clsb[j];
        for (int k = 0; k < 1024; k++) acc = fmaf(hp[k], clsw[k*6 + j], acc);
        logits[r*6 + j] = acc;
    } else {
        int q = j - 6;
        float acc = bbb[q];
        for (int k = 0; k < 1024; k++) acc = fmaf(hp[k], bbw[k*24 + q], acc);
        breg[r*24 + q] = acc;
    }
}

// ---------------- final: softmax + per-class decode + clip + pack output ----------------
__global__ void final_kernel(const float* __restrict__ rois,
                             const float* __restrict__ logits,
                             const float* __restrict__ breg,
                             float* __restrict__ out) {
    int r = blockIdx.x * 128 + threadIdx.x;
    if (r >= TOPN) return;
    float l[6];
    float m = -INFINITY;
    #pragma unroll
    for (int i = 0; i < 6; i++) { l[i] = logits[r*6 + i]; m = fmaxf(m, l[i]); }
    float ssum = 0.0f;
    #pragma unroll
    for (int i = 0; i < 6; i++) { l[i] = expf(l[i] - m); ssum += l[i]; }
    float inv = 1.0f / ssum;

    float x1 = rois[r*4+0], y1 = rois[r*4+1], x2 = rois[r*4+2], y2 = rois[r*4+3];
    float W = x2 - x1, H = y2 - y1;
    float cx = x1 + 0.5f*W, cy = y1 + 0.5f*H;
    #pragma unroll
    for (int c = 1; c < 6; c++) {
        float dx = breg[r*24 + c*4+0] / 10.0f;
        float dy = breg[r*24 + c*4+1] / 10.0f;
        float dw = fminf(breg[r*24 + c*4+2] / 5.0f, BBOX_CLAMP);
        float dh = fminf(breg[r*24 + c*4+3] / 5.0f, BBOX_CLAMP);
        float pcx = dx*W + cx, pcy = dy*H + cy;
        float pw = expf(dw)*W, ph = expf(dh)*H;
        float bx1 = fminf(fmaxf(pcx - 0.5f*pw, 0.0f), 512.0f);
        float by1 = fminf(fmaxf(pcy - 0.5f*ph, 0.0f), 512.0f);
        float bx2 = fminf(fmaxf(pcx + 0.5f*pw, 0.0f), 512.0f);
        float by2 = fminf(fmaxf(pcy + 0.5f*ph, 0.0f), 512.0f);
        int o = r*25 + (c-1)*5;
        out[o+0] = bx1; out[o+1] = by1; out[o+2] = bx2; out[o+3] = by2;
        out[o+4] = l[c] * inv;
    }
}

// ---------------- launcher ----------------
extern "C" void kernel_launch(void* const* d_in, const int* in_sizes, int n_in,
                              void* d_out, int out_size) {
    const float* images     = (const float*)d_in[0];
    const float* c0_w       = (const float*)d_in[1];
    const float* c0_b       = (const float*)d_in[2];
    const float* c1_w       = (const float*)d_in[3];
    const float* c1_b       = (const float*)d_in[4];
    const float* c2_w       = (const float*)d_in[5];
    const float* c2_b       = (const float*)d_in[6];
    const float* c3_w       = (const float*)d_in[7];
    const float* c3_b       = (const float*)d_in[8];
    const float* rpn_conv_w = (const float*)d_in[9];
    const float* rpn_conv_b = (const float*)d_in[10];
    const float* rpn_cls_w  = (const float*)d_in[11];
    const float* rpn_cls_b  = (const float*)d_in[12];
    const float* rpn_bbox_w = (const float*)d_in[13];
    const float* rpn_bbox_b = (const float*)d_in[14];
    const float* fc1_w      = (const float*)d_in[15];
    const float* fc1_b      = (const float*)d_in[16];
    const float* fc2_w      = (const float*)d_in[17];
    const float* fc2_b      = (const float*)d_in[18];
    const float* cls_w      = (const float*)d_in[19];
    const float* cls_b      = (const float*)d_in[20];
    const float* bbox_w     = (const float*)d_in[21];
    const float* bbox_b     = (const float*)d_in[22];
    float* out = (float*)d_out;

    float *p_c0, *p_pool, *p_c1, *p_c2, *p_feat, *p_rpn, *p_obj, *p_bd;
    float *p_props, *p_scores, *p_rois, *p_bf, *p_h1, *p_h2, *p_logits, *p_breg;
    int *p_topidx;
    cudaGetSymbolAddress((void**)&p_c0, g_c0);
    cudaGetSymbolAddress((void**)&p_pool, g_pool);
    cudaGetSymbolAddress((void**)&p_c1, g_c1);
    cudaGetSymbolAddress((void**)&p_c2, g_c2);
    cudaGetSymbolAddress((void**)&p_feat, g_feat);
    cudaGetSymbolAddress((void**)&p_rpn, g_rpn);
    cudaGetSymbolAddress((void**)&p_obj, g_obj);
    cudaGetSymbolAddress((void**)&p_bd, g_bd);
    cudaGetSymbolAddress((void**)&p_props, g_props);
    cudaGetSymbolAddress((void**)&p_scores, g_scores);
    cudaGetSymbolAddress((void**)&p_topidx, g_topidx);
    cudaGetSymbolAddress((void**)&p_rois, g_rois);
    cudaGetSymbolAddress((void**)&p_bf, g_bf);
    cudaGetSymbolAddress((void**)&p_h1, g_h1);
    cudaGetSymbolAddress((void**)&p_h2, g_h2);
    cudaGetSymbolAddress((void**)&p_logits, g_logits);
    cudaGetSymbolAddress((void**)&p_breg, g_breg);

    // backbone
    conv0_kernel<<<dim3(16,16,64), dim3(16,16)>>>(images, c0_w, c0_b, p_c0);
    maxpool_kernel<<<(64*128*128 + 255)/256, 256>>>(p_c0, p_pool);
    conv3x3_kernel<<<dim3(4,4,128), dim3(16,16),  64*9*4>>>(p_pool, c1_w, c1_b, p_c1, 64, 128, 64, 2);
    conv3x3_kernel<<<dim3(2,2,256), dim3(16,16), 128*9*4>>>(p_c1, c2_w, c2_b, p_c2, 128, 64, 32, 2);
    conv3x3_kernel<<<dim3(1,1,512), dim3(16,16), 256*9*4>>>(p_c2, c3_w, c3_b, p_feat, 256, 32, 16, 2);

    // RPN
    conv3x3_kernel<<<dim3(1,1,512), dim3(16,16), 512*9*4>>>(p_feat, rpn_conv_w, rpn_conv_b, p_rpn, 512, 16, 16, 1);
    conv1x1_kernel<<<9, 256>>>(p_rpn, rpn_cls_w, rpn_cls_b, p_obj, 512);
    conv1x1_kernel<<<36, 256>>>(p_rpn, rpn_bbox_w, rpn_bbox_b, p_bd, 512);

    // proposals
    rpn_decode_kernel<<<9, 256>>>(p_obj, p_bd, p_props, p_scores);
    topk_kernel<<<1, 1024>>>(p_scores, p_topidx);
    gather_rois_kernel<<<4, 256>>>(p_props, p_topidx, p_rois);

    // roi align + head
    roi_align_kernel<<<TOPN, 256>>>(p_feat, p_rois, p_bf);
    gemm_bias_kernel<<<dim3(1024/64, (TOPN+63)/64), 256>>>(p_bf, fc1_w, fc1_b, p_h1, TOPN, 1024, 25088, 1);
    gemm_bias_kernel<<<dim3(1024/64, (TOPN+63)/64), 256>>>(p_h1, fc2_w, fc2_b, p_h2, TOPN, 1024, 1024, 1);
    fc_small_kernel<<<(TOPN*30 + 127)/128, 128>>>(p_h2, cls_w, cls_b, bbox_w, bbox_b, p_logits, p_breg);
    final_kernel<<<(TOPN + 127)/128, 128>>>(p_rois, p_logits, p_breg, out);
}

// round 2
// speedup vs baseline: 2.2654x; 2.2654x over previous
#include <cuda_runtime.h>
#include <cuda_bf16.h>
#include <math.h>
#include <stdint.h>

#define TOPN 1000
#define BBOX_CLAMP 4.135166556742356f
typedef unsigned short u16;

// ---------------- scratch (device globals) ----------------
__device__ float g_c0[64*256*256];
__device__ float g_pool[64*128*128];
__device__ float g_c1[128*64*64];
__device__ float g_c2[256*32*32];
__device__ float g_feat[512*16*16];
__device__ float g_rpn[512*16*16];
__device__ float g_obj[9*16*16];
__device__ float g_bd[36*16*16];
__device__ float g_props[2304*4];
__device__ float g_scores[2304];
__device__ int   g_topidx[TOPN];
__device__ float g_rois[TOPN*4];
// split-bf16 buffers (stored as u16 bits)
__device__ u16 g_Ah[1024u*25088u];   // roi features hi, [1024][25088]
__device__ u16 g_Al[1024u*25088u];
__device__ u16 g_B1h[1024u*25088u];  // fc1_w^T hi, [1024][25088]
__device__ u16 g_B1l[1024u*25088u];
__device__ u16 g_B2h[1024u*1024u];   // fc2_w^T
__device__ u16 g_B2l[1024u*1024u];
__device__ u16 g_h1h[1024u*1024u];   // fc1 output split
__device__ u16 g_h1l[1024u*1024u];
__device__ float g_part[16u*1024u*1024u]; // K-split partials
__device__ float g_h2[1024u*1024u];
__device__ float g_logits[TOPN*6];
__device__ float g_breg[TOPN*24];

// ---------------- conv0: 7x7 s2 p3, 3->64, fused normalize+relu ----------------
__global__ void conv0_kernel(const float* __restrict__ img,
                             const float* __restrict__ w,
                             const float* __restrict__ b,
                             float* __restrict__ out) {
    __shared__ float ws[3*49];
    int o = blockIdx.z;
    int tid = threadIdx.y * 16 + threadIdx.x;
    if (tid < 147) ws[tid] = w[o*147 + tid];
    __syncthreads();
    int x = blockIdx.x * 16 + threadIdx.x;
    int y = blockIdx.y * 16 + threadIdx.y;
    const float mean[3] = {0.485f, 0.456f, 0.406f};
    const float stdv[3] = {0.229f, 0.224f, 0.225f};
    float acc = b[o];
    #pragma unroll
    for (int c = 0; c < 3; c++) {
        float istd = 1.0f / stdv[c];
        #pragma unroll
        for (int ky = 0; ky < 7; ky++) {
            int iy = 2*y - 3 + ky;
            if (iy < 0 || iy >= 512) continue;
            #pragma unroll
            for (int kx = 0; kx < 7; kx++) {
                int ix = 2*x - 3 + kx;
                if (ix < 0 || ix >= 512) continue;
                float v = (img[(c*512 + iy)*512 + ix] - mean[c]) * istd;
                acc = fmaf(v, ws[c*49 + ky*7 + kx], acc);
            }
        }
    }
    out[(o*256 + y)*256 + x] = fmaxf(acc, 0.0f);
}

// ---------------- maxpool 3x3 s2 p1 ----------------
__global__ void maxpool_kernel(const float* __restrict__ in, float* __restrict__ out) {
    int idx = blockIdx.x * 256 + threadIdx.x;
    if (idx >= 64*128*128) return;
    int x = idx & 127;
    int y = (idx >> 7) & 127;
    int c = idx >> 14;
    float m = -INFINITY;
    #pragma unroll
    for (int dy = 0; dy < 3; dy++) {
        int iy = 2*y - 1 + dy;
        if (iy < 0 || iy >= 256) continue;
        #pragma unroll
        for (int dx = 0; dx < 3; dx++) {
            int ix = 2*x - 1 + dx;
            if (ix < 0 || ix >= 256) continue;
            m = fmaxf(m, in[(c*256 + iy)*256 + ix]);
        }
    }
    out[idx] = m;
}

// ---------------- 3x3 conv v2: 4 output channels per thread ----------------
__global__ void conv3x3v2_kernel(const float* __restrict__ in,
                                 const float* __restrict__ w,
                                 const float* __restrict__ b,
                                 float* __restrict__ out,
                                 int Cin, int Hin, int Hout, int stride, int chunk) {
    extern __shared__ float ws[];   // [4][chunk*9]
    int oc0 = blockIdx.z * 4;
    int tid = threadIdx.y * 16 + threadIdx.x;
    int x = blockIdx.x * 16 + threadIdx.x;
    int y = blockIdx.y * 16 + threadIdx.y;
    int iy0 = y*stride - 1, ix0 = x*stride - 1;
    int chunk9 = chunk * 9;
    float acc0 = b[oc0+0], acc1 = b[oc0+1], acc2 = b[oc0+2], acc3 = b[oc0+3];

    for (int c0 = 0; c0 < Cin; c0 += chunk) {
        __syncthreads();
        for (int i = tid; i < 4*chunk9; i += 256) {
            int o = i / chunk9, j = i - o*chunk9;
            ws[i] = w[(size_t)(oc0+o)*Cin*9 + (size_t)c0*9 + j];
        }
        __syncthreads();
        const float* wp0 = ws;
        const float* wp1 = ws + chunk9;
        const float* wp2 = ws + 2*chunk9;
        const float* wp3 = ws + 3*chunk9;
        for (int cl = 0; cl < chunk; cl++) {
            const float* ip = in + (size_t)(c0+cl)*Hin*Hin;
            float v[9];
            #pragma unroll
            for (int ky = 0; ky < 3; ky++) {
                int iy = iy0 + ky;
                bool oky = (iy >= 0 && iy < Hin);
                #pragma unroll
                for (int kx = 0; kx < 3; kx++) {
                    int ix = ix0 + kx;
                    v[ky*3+kx] = (oky && ix >= 0 && ix < Hin) ? ip[iy*Hin + ix] : 0.0f;
                }
            }
            int base = cl*9;
            #pragma unroll
            for (int k = 0; k < 9; k++) {
                float vk = v[k];
                acc0 = fmaf(vk, wp0[base+k], acc0);
                acc1 = fmaf(vk, wp1[base+k], acc1);
                acc2 = fmaf(vk, wp2[base+k], acc2);
                acc3 = fmaf(vk, wp3[base+k], acc3);
            }
        }
    }
    size_t pix = (size_t)y*Hout + x;
    size_t plane = (size_t)Hout*Hout;
    out[(size_t)(oc0+0)*plane + pix] = fmaxf(acc0, 0.0f);
    out[(size_t)(oc0+1)*plane + pix] = fmaxf(acc1, 0.0f);
    out[(size_t)(oc0+2)*plane + pix] = fmaxf(acc2, 0.0f);
    out[(size_t)(oc0+3)*plane + pix] = fmaxf(acc3, 0.0f);
}

// ---------------- 1x1 conv over 16x16 plane ----------------
__global__ void conv1x1_kernel(const float* __restrict__ in,
                               const float* __restrict__ w,
                               const float* __restrict__ b,
                               float* __restrict__ out, int Cin) {
    int p = threadIdx.x;
    int o = blockIdx.x;
    float acc = b[o];
    for (int c = 0; c < Cin; c++)
        acc = fmaf(in[c*256 + p], w[o*Cin + c], acc);
    out[o*256 + p] = acc;
}

// ---------------- RPN decode ----------------
__global__ void rpn_decode_kernel(const float* __restrict__ obj,
                                  const float* __restrict__ bd,
                                  float* __restrict__ props,
                                  float* __restrict__ scores) {
    int i = blockIdx.x * 256 + threadIdx.x;
    if (i >= 2304) return;
    int a = i % 9;
    int cell = i / 9;
    int wq = cell % 16;
    int hq = cell / 16;
    int pix = hq*16 + wq;
    scores[i] = obj[a*256 + pix];

    const float ratios[3] = {0.5f, 1.0f, 2.0f};
    int r = a / 3, s = a % 3;
    float scale = 128.0f * (float)(1 << s);
    float hr = sqrtf(ratios[r]);
    float wr = 1.0f / hr;
    float hw = rintf(wr * scale * 0.5f);
    float hh = rintf(hr * scale * 0.5f);
    float sx = (float)(wq * 32), sy = (float)(hq * 32);
    float W = 2.0f*hw, H = 2.0f*hh;
    float cx = sx, cy = sy;

    float dx = bd[(a*4+0)*256 + pix];
    float dy = bd[(a*4+1)*256 + pix];
    float dw = fminf(bd[(a*4+2)*256 + pix], BBOX_CLAMP);
    float dh = fminf(bd[(a*4+3)*256 + pix], BBOX_CLAMP);
    float pcx = dx*W + cx, pcy = dy*H + cy;
    float pw = expf(dw)*W, ph = expf(dh)*H;
    props[i*4+0] = pcx - 0.5f*pw;
    props[i*4+1] = pcy - 0.5f*ph;
    props[i*4+2] = pcx + 0.5f*pw;
    props[i*4+3] = pcy + 0.5f*ph;
}

// ---------------- top-k bitonic ----------------
__device__ __forceinline__ bool tk_lt(float sa, int ia, float sb, int ib) {
    return (sa > sb) || (sa == sb && ia < ib);
}
__global__ void topk_kernel(const float* __restrict__ scores, int* __restrict__ topidx) {
    __shared__ float s[4096];
    __shared__ int   ind[4096];
    int tid = threadIdx.x;
    for (int i = tid; i < 4096; i += 1024) {
        s[i] = (i < 2304) ? scores[i] : -INFINITY;
        ind[i] = i;
    }
    __syncthreads();
    for (int k = 2; k <= 4096; k <<= 1) {
        for (int j = k >> 1; j > 0; j >>= 1) {
            for (int base = 0; base < 4096; base += 1024) {
                int i = base + tid;
                int ixj = i ^ j;
                if (ixj > i) {
                    bool up = ((i & k) == 0);
                    float si = s[i], sj = s[ixj];
                    int ii = ind[i], ij = ind[ixj];
                    bool swp = up ? tk_lt(sj, ij, si, ii) : tk_lt(si, ii, sj, ij);
                    if (swp) { s[i] = sj; s[ixj] = si; ind[i] = ij; ind[ixj] = ii; }
                }
            }
            __syncthreads();
        }
    }
    for (int i = tid; i < TOPN; i += 1024) topidx[i] = ind[i];
}

__global__ void gather_rois_kernel(const float* __restrict__ props,
                                   const int* __restrict__ topidx,
                                   float* __restrict__ rois) {
    int i = blockIdx.x * 256 + threadIdx.x;
    if (i >= TOPN) return;
    int idx = topidx[i];
    #pragma unroll
    for (int k = 0; k < 4; k++)
        rois[i*4+k] = fminf(fmaxf(props[idx*4+k], 0.0f), 512.0f);
}

// ---------------- ROI align -> split-bf16 A matrix ----------------
__global__ void roi_align_kernel(const float* __restrict__ feat,
                                 const float* __restrict__ rois,
                                 u16* __restrict__ Ah, u16* __restrict__ Al) {
    __shared__ int   sx0[14], sx1[14], sy0[14], sy1[14];
    __shared__ float slx[14], sly[14];
    int r = blockIdx.x;
    int tid = threadIdx.x;
    if (tid < 28) {
        int i = tid % 14;
        bool isY = tid >= 14;
        float c1 = rois[r*4 + (isY ? 1 : 0)];
        float c2 = rois[r*4 + (isY ? 3 : 2)];
        float lo = c1 * (1.0f/32.0f);
        float hi = c2 * (1.0f/32.0f);
        float sz = fmaxf(hi - lo, 1.0f);
        float g = ((float)i + 0.5f) / 14.0f;
        float p = fminf(fmaxf(lo + g*sz, 0.0f), 15.0f);
        int p0 = (int)floorf(p);
        int p1 = min(p0 + 1, 15);
        float l = p - (float)p0;
        if (isY) { sy0[i] = p0; sy1[i] = p1; sly[i] = l; }
        else     { sx0[i] = p0; sx1[i] = p1; slx[i] = l; }
    }
    __syncthreads();
    for (int j = tid; j < 25088; j += 256) {
        int c = j / 49;
        int p = j % 49;
        int py = p / 7, px = p % 7;
        const float* fp = feat + c*256;
        float acc = 0.0f;
        #pragma unroll
        for (int dy = 0; dy < 2; dy++) {
            int iy = py*2 + dy;
            float ly = sly[iy], hy = 1.0f - ly;
            int y0 = sy0[iy], y1 = sy1[iy];
            #pragma unroll
            for (int dx = 0; dx < 2; dx++) {
                int ix = px*2 + dx;
                float lx = slx[ix], hx = 1.0f - lx;
                int x0 = sx0[ix], x1 = sx1[ix];
                acc += hy*hx*fp[y0*16+x0] + hy*lx*fp[y0*16+x1]
                     + ly*hx*fp[y1*16+x0] + ly*lx*fp[y1*16+x1];
            }
        }
        float v = acc * 0.25f;
        __nv_bfloat16 h = __float2bfloat16(v);
        float res = v - __bfloat162float(h);
        __nv_bfloat16 l = __float2bfloat16(res);
        size_t o = (size_t)r*25088 + j;
        Ah[o] = *(u16*)&h;
        Al[o] = *(u16*)&l;
    }
}

// zero pad rows [1000,1024) of A
__global__ void padA_kernel(u16* __restrict__ Ah, u16* __restrict__ Al) {
    size_t idx = (size_t)blockIdx.x * 256 + threadIdx.x;
    size_t total = 24u*25088u;
    if (idx >= total) return;
    size_t o = (size_t)1000*25088 + idx;
    Ah[o] = 0; Al[o] = 0;
}

// ---------------- transpose + bf16-split weights: W[K][N] -> T[N][K] hi/lo ----------------
__global__ void tsplit_kernel(const float* __restrict__ W,
                              u16* __restrict__ Th, u16* __restrict__ Tl,
                              int K, int N) {
    __shared__ float t[32][33];
    int n0 = blockIdx.x * 32, k0 = blockIdx.y * 32;
    int tx = threadIdx.x, ty = threadIdx.y;
    #pragma unroll
    for (int i = 0; i < 4; i++)
        t[ty + 8*i][tx] = W[(size_t)(k0 + ty + 8*i)*N + n0 + tx];
    __syncthreads();
    #pragma unroll
    for (int i = 0; i < 4; i++) {
        float v = t[tx][ty + 8*i];
        __nv_bfloat16 h = __float2bfloat16(v);
        float res = v - __bfloat162float(h);
        __nv_bfloat16 l = __float2bfloat16(res);
        size_t o = (size_t)(n0 + ty + 8*i)*K + k0 + tx;
        Th[o] = *(u16*)&h;
        Tl[o] = *(u16*)&l;
    }
}

// ---------------- split-bf16 tensor-core GEMM ----------------
// C_part[z] += A[1024,K_chunk] @ B^T[1024,K_chunk]^T ; 3-term bf16 split.
// BM=BN=128, BK=16, 256 threads (8 warps, 2x4), warp tile 64x32.
__device__ __forceinline__ void mma16816(float& d0, float& d1, float& d2, float& d3,
                                         uint32_t a0, uint32_t a1, uint32_t a2, uint32_t a3,
                                         uint32_t b0, uint32_t b1) {
    asm volatile("mma.sync.aligned.m16n8k16.row.col.f32.bf16.bf16.f32 "
                 "{%0,%1,%2,%3}, {%4,%5,%6,%7}, {%8,%9}, {%0,%1,%2,%3};\n"
                 : "+f"(d0), "+f"(d1), "+f"(d2), "+f"(d3)
                 : "r"(a0), "r"(a1), "r"(a2), "r"(a3), "r"(b0), "r"(b1));
}
__device__ __forceinline__ void cpasync16(uint32_t dst, const void* src) {
    asm volatile("cp.async.cg.shared.global [%0], [%1], 16;\n" :: "r"(dst), "l"(src));
}
__device__ __forceinline__ uint32_t lds32(const u16* p) {
    return *reinterpret_cast<const uint32_t*>(p);
}

#define LDK 24   // bf16 elems per smem row (48 bytes, 16B multiple)

__global__ void __launch_bounds__(256, 1)
gemm_split_kernel(const u16* __restrict__ Ah, const u16* __restrict__ Al,
                  const u16* __restrict__ Bh, const u16* __restrict__ Bl,
                  float* __restrict__ part, int K, int stages) {
    __shared__ __align__(16) u16 sm[2][4][128*LDK];  // [stage][Ah,Al,Bh,Bl]
    int tid = threadIdx.x;
    int wid = tid >> 5, lane = tid & 31;
    int wm = (wid & 1) * 64;        // warp row offset
    int wn = (wid >> 1) * 32;       // warp col offset
    int g = lane >> 2, tig = lane & 3;
    int bm = blockIdx.y * 128, bn = blockIdx.x * 128;
    int kbase = blockIdx.z * stages * 16;

    float acc[16][4];
    #pragma unroll
    for (int i = 0; i < 16; i++)
        #pragma unroll
        for (int j = 0; j < 4; j++) acc[i][j] = 0.0f;

    // stage loader
    auto load_stage = [&](int buf, int s) {
        int kpos0 = kbase + s * 16;
        #pragma unroll
        for (int l = 0; l < 4; l++) {
            int idx = l * 256 + tid;
            int pl = idx >> 8;
            int r = (idx & 255) >> 1;
            int half = idx & 1;
            int kpos = kpos0 + half * 8;
            const u16* src;
            if (pl == 0)      src = Ah + (size_t)(bm + r)*K + kpos;
            else if (pl == 1) src = Al + (size_t)(bm + r)*K + kpos;
            else if (pl == 2) src = Bh + (size_t)(bn + r)*K + kpos;
            else              src = Bl + (size_t)(bn + r)*K + kpos;
            uint32_t dst = (uint32_t)__cvta_generic_to_shared(&sm[buf][pl][r*LDK + half*8]);
            cpasync16(dst, src);
        }
        asm volatile("cp.async.commit_group;\n");
    };

    load_stage(0, 0);

    for (int s = 0; s < stages; s++) {
        if (s + 1 < stages) {
            load_stage((s + 1) & 1, s + 1);
            asm volatile("cp.async.wait_group 1;\n");
        } else {
            asm volatile("cp.async.wait_group 0;\n");
        }
        __syncthreads();
        int b = s & 1;
        const u16* pAh = sm[b][0];
        const u16* pAl = sm[b][1];
        const u16* pBh = sm[b][2];
        const u16* pBl = sm[b][3];

        uint32_t Bh0[4], Bh1[4], Bl0[4], Bl1[4];
        #pragma unroll
        for (int ni = 0; ni < 4; ni++) {
            int off = (wn + ni*8 + g)*LDK + 2*tig;
            Bh0[ni] = lds32(pBh + off);
            Bh1[ni] = lds32(pBh + off + 8);
            Bl0[ni] = lds32(pBl + off);
            Bl1[ni] = lds32(pBl + off + 8);
        }
        #pragma unroll
        for (int mi = 0; mi < 4; mi++) {
            int off = (wm + mi*16 + g)*LDK + 2*tig;
            uint32_t ah0 = lds32(pAh + off);
            uint32_t ah1 = lds32(pAh + off + 8*LDK);
            uint32_t ah2 = lds32(pAh + off + 8);
            uint32_t ah3 = lds32(pAh + off + 8*LDK + 8);
            uint32_t al0 = lds32(pAl + off);
            uint32_t al1 = lds32(pAl + off + 8*LDK);
            uint32_t al2 = lds32(pAl + off + 8);
            uint32_t al3 = lds32(pAl + off + 8*LDK + 8);
            #pragma unroll
            for (int ni = 0; ni < 4; ni++) {
                float* d = acc[mi*4 + ni];
                mma16816(d[0], d[1], d[2], d[3], ah0, ah1, ah2, ah3, Bh0[ni], Bh1[ni]);
                mma16816(d[0], d[1], d[2], d[3], ah0, ah1, ah2, ah3, Bl0[ni], Bl1[ni]);
                mma16816(d[0], d[1], d[2], d[3], al0, al1, al2, al3, Bh0[ni], Bh1[ni]);
            }
        }
        __syncthreads();
    }

    float* cbase = part + ((size_t)blockIdx.z << 20);
    #pragma unroll
    for (int mi = 0; mi < 4; mi++) {
        #pragma unroll
        for (int ni = 0; ni < 4; ni++) {
            int row = bm + wm + mi*16 + g;
            int col = bn + wn + ni*8 + 2*tig;
            float* d = acc[mi*4 + ni];
            *(float2*)&cbase[(size_t)row*1024 + col]     = make_float2(d[0], d[1]);
            *(float2*)&cbase[(size_t)(row+8)*1024 + col] = make_float2(d[2], d[3]);
        }
    }
}

// reduce fc1 partials -> relu -> split-bf16 h1
__global__ void reduce1_kernel(const float* __restrict__ part,
                               const float* __restrict__ bias,
                               u16* __restrict__ Hh, u16* __restrict__ Hl) {
    size_t idx = (size_t)blockIdx.x * 256 + threadIdx.x;
    int n = (int)(idx & 1023);
    float s = bias[n];
    #pragma unroll
    for (int i = 0; i < 16; i++) s += part[((size_t)i << 20) + idx];
    s = fmaxf(s, 0.0f);
    __nv_bfloat16 h = __float2bfloat16(s);
    float res = s - __bfloat162float(h);
    __nv_bfloat16 l = __float2bfloat16(res);
    Hh[idx] = *(u16*)&h;
    Hl[idx] = *(u16*)&l;
}

// reduce fc2 partials -> relu -> f32 h2
__global__ void reduce2_kernel(const float* __restrict__ part,
                               const float* __restrict__ bias,
                               float* __restrict__ H) {
    size_t idx = (size_t)blockIdx.x * 256 + threadIdx.x;
    int n = (int)(idx & 1023);
    float s = bias[n];
    #pragma unroll
    for (int i = 0; i < 4; i++) s += part[((size_t)i << 20) + idx];
    H[idx] = fmaxf(s, 0.0f);
}

// ---------------- cls + bbox heads ----------------
__global__ void fc_small_kernel(const float* __restrict__ h,
                                const float* __restrict__ clsw, const float* __restrict__ clsb,
                                const float* __restrict__ bbw, const float* __restrict__ bbb,
                                float* __restrict__ logits, float* __restrict__ breg) {
    int t = blockIdx.x * 128 + threadIdx.x;
    if (t >= TOPN * 30) return;
    int r = t / 30, j = t % 30;
    const float* hp = h + (size_t)r*1024;
    if (j < 6) {
        float acc = clsb[j];
        for (int k = 0; k < 1024; k++) acc = fmaf(hp[k], clsw[k*6 + j], acc);
        logits[r*6 + j] = acc;
    } else {
        int q = j - 6;
        float acc = bbb[q];
        for (int k = 0; k < 1024; k++) acc = fmaf(hp[k], bbw[k*24 + q], acc);
        breg[r*24 + q] = acc;
    }
}

// ---------------- final ----------------
__global__ void final_kernel(const float* __restrict__ rois,
                             const float* __restrict__ logits,
                             const float* __restrict__ breg,
                             float* __restrict__ out) {
    int r = blockIdx.x * 128 + threadIdx.x;
    if (r >= TOPN) return;
    float l[6];
    float m = -INFINITY;
    #pragma unroll
    for (int i = 0; i < 6; i++) { l[i] = logits[r*6 + i]; m = fmaxf(m, l[i]); }
    float ssum = 0.0f;
    #pragma unroll
    for (int i = 0; i < 6; i++) { l[i] = expf(l[i] - m); ssum += l[i]; }
    float inv = 1.0f / ssum;

    float x1 = rois[r*4+0], y1 = rois[r*4+1], x2 = rois[r*4+2], y2 = rois[r*4+3];
    float W = x2 - x1, H = y2 - y1;
    float cx = x1 + 0.5f*W, cy = y1 + 0.5f*H;
    #pragma unroll
    for (int c = 1; c < 6; c++) {
        float dx = breg[r*24 + c*4+0] / 10.0f;
        float dy = breg[r*24 + c*4+1] / 10.0f;
        float dw = fminf(breg[r*24 + c*4+2] / 5.0f, BBOX_CLAMP);
        float dh = fminf(breg[r*24 + c*4+3] / 5.0f, BBOX_CLAMP);
        float pcx = dx*W + cx, pcy = dy*H + cy;
        float pw = expf(dw)*W, ph = expf(dh)*H;
        float bx1 = fminf(fmaxf(pcx - 0.5f*pw, 0.0f), 512.0f);
        float by1 = fminf(fmaxf(pcy - 0.5f*ph, 0.0f), 512.0f);
        float bx2 = fminf(fmaxf(pcx + 0.5f*pw, 0.0f), 512.0f);
        float by2 = fminf(fmaxf(pcy + 0.5f*ph, 0.0f), 512.0f);
        int o = r*25 + (c-1)*5;
        out[o+0] = bx1; out[o+1] = by1; out[o+2] = bx2; out[o+3] = by2;
        out[o+4] = l[c] * inv;
    }
}

// ---------------- launcher ----------------
extern "C" void kernel_launch(void* const* d_in, const int* in_sizes, int n_in,
                              void* d_out, int out_size) {
    const float* images     = (const float*)d_in[0];
    const float* c0_w       = (const float*)d_in[1];
    const float* c0_b       = (const float*)d_in[2];
    const float* c1_w       = (const float*)d_in[3];
    const float* c1_b       = (const float*)d_in[4];
    const float* c2_w       = (const float*)d_in[5];
    const float* c2_b       = (const float*)d_in[6];
    const float* c3_w       = (const float*)d_in[7];
    const float* c3_b       = (const float*)d_in[8];
    const float* rpn_conv_w = (const float*)d_in[9];
    const float* rpn_conv_b = (const float*)d_in[10];
    const float* rpn_cls_w  = (const float*)d_in[11];
    const float* rpn_cls_b  = (const float*)d_in[12];
    const float* rpn_bbox_w = (const float*)d_in[13];
    const float* rpn_bbox_b = (const float*)d_in[14];
    const float* fc1_w      = (const float*)d_in[15];
    const float* fc1_b      = (const float*)d_in[16];
    const float* fc2_w      = (const float*)d_in[17];
    const float* fc2_b      = (const float*)d_in[18];
    const float* cls_w      = (const float*)d_in[19];
    const float* cls_b      = (const float*)d_in[20];
    const float* bbox_w     = (const float*)d_in[21];
    const float* bbox_b     = (const float*)d_in[22];
    float* out = (float*)d_out;

    float *p_c0, *p_pool, *p_c1, *p_c2, *p_feat, *p_rpn, *p_obj, *p_bd;
    float *p_props, *p_scores, *p_rois, *p_part, *p_h2, *p_logits, *p_breg;
    int *p_topidx;
    u16 *p_Ah, *p_Al, *p_B1h, *p_B1l, *p_B2h, *p_B2l, *p_h1h, *p_h1l;
    cudaGetSymbolAddress((void**)&p_c0, g_c0);
    cudaGetSymbolAddress((void**)&p_pool, g_pool);
    cudaGetSymbolAddress((void**)&p_c1, g_c1);
    cudaGetSymbolAddress((void**)&p_c2, g_c2);
    cudaGetSymbolAddress((void**)&p_feat, g_feat);
    cudaGetSymbolAddress((void**)&p_rpn, g_rpn);
    cudaGetSymbolAddress((void**)&p_obj, g_obj);
    cudaGetSymbolAddress((void**)&p_bd, g_bd);
    cudaGetSymbolAddress((void**)&p_props, g_props);
    cudaGetSymbolAddress((void**)&p_scores, g_scores);
    cudaGetSymbolAddress((void**)&p_topidx, g_topidx);
    cudaGetSymbolAddress((void**)&p_rois, g_rois);
    cudaGetSymbolAddress((void**)&p_Ah, g_Ah);
    cudaGetSymbolAddress((void**)&p_Al, g_Al);
    cudaGetSymbolAddress((void**)&p_B1h, g_B1h);
    cudaGetSymbolAddress((void**)&p_B1l, g_B1l);
    cudaGetSymbolAddress((void**)&p_B2h, g_B2h);
    cudaGetSymbolAddress((void**)&p_B2l, g_B2l);
    cudaGetSymbolAddress((void**)&p_h1h, g_h1h);
    cudaGetSymbolAddress((void**)&p_h1l, g_h1l);
    cudaGetSymbolAddress((void**)&p_part, g_part);
    cudaGetSymbolAddress((void**)&p_h2, g_h2);
    cudaGetSymbolAddress((void**)&p_logits, g_logits);
    cudaGetSymbolAddress((void**)&p_breg, g_breg);

    // weight transpose+split (independent of data path)
    tsplit_kernel<<<dim3(1024/32, 25088/32), dim3(32,8)>>>(fc1_w, p_B1h, p_B1l, 25088, 1024);
    tsplit_kernel<<<dim3(1024/32, 1024/32),  dim3(32,8)>>>(fc2_w, p_B2h, p_B2l, 1024, 1024);

    // backbone
    conv0_kernel<<<dim3(16,16,64), dim3(16,16)>>>(images, c0_w, c0_b, p_c0);
    maxpool_kernel<<<(64*128*128 + 255)/256, 256>>>(p_c0, p_pool);
    conv3x3v2_kernel<<<dim3(4,4,32), dim3(16,16),  4*64*9*4>>>(p_pool, c1_w, c1_b, p_c1, 64, 128, 64, 2, 64);
    conv3x3v2_kernel<<<dim3(2,2,64), dim3(16,16), 4*128*9*4>>>(p_c1, c2_w, c2_b, p_c2, 128, 64, 32, 2, 128);
    conv3x3v2_kernel<<<dim3(1,1,128), dim3(16,16), 4*128*9*4>>>(p_c2, c3_w, c3_b, p_feat, 256, 32, 16, 2, 128);

    // RPN
    conv3x3v2_kernel<<<dim3(1,1,128), dim3(16,16), 4*128*9*4>>>(p_feat, rpn_conv_w, rpn_conv_b, p_rpn, 512, 16, 16, 1, 128);
    conv1x1_kernel<<<9, 256>>>(p_rpn, rpn_cls_w, rpn_cls_b, p_obj, 512);
    conv1x1_kernel<<<36, 256>>>(p_rpn, rpn_bbox_w, rpn_bbox_b, p_bd, 512);

    // proposals
    rpn_decode_kernel<<<9, 256>>>(p_obj, p_bd, p_props, p_scores);
    topk_kernel<<<1, 1024>>>(p_scores, p_topidx);
    gather_rois_kernel<<<4, 256>>>(p_props, p_topidx, p_rois);

    // roi align -> split A
    roi_align_kernel<<<TOPN, 256>>>(p_feat, p_rois, p_Ah, p_Al);
    padA_kernel<<<(24*25088 + 255)/256, 256>>>(p_Ah, p_Al);

    // fc1: K=25088, KSPLIT=16 -> stages = 25088/(16*16) = 98
    gemm_split_kernel<<<dim3(8,8,16), 256>>>(p_Ah, p_Al, p_B1h, p_B1l, p_part, 25088, 98);
    reduce1_kernel<<<(1024*1024)/256, 256>>>(p_part, fc1_b, p_h1h, p_h1l);

    // fc2: K=1024, KSPLIT=4 -> stages = 1024/(16*4) = 16
    gemm_split_kernel<<<dim3(8,8,4), 256>>>(p_h1h, p_h1l, p_B2h, p_B2l, p_part, 1024, 16);
    reduce2_kernel<<<(1024*1024)/256, 256>>>(p_part, fc2_b, p_h2);

    fc_small_kernel<<<(TOPN*30 + 127)/128, 128>>>(p_h2, cls_w, cls_b, bbox_w, bbox_b, p_logits, p_breg);
    final_kernel<<<(TOPN + 127)/128, 128>>>(p_rois, p_logits, p_breg, out);
}